// round 1
// baseline (speedup 1.0000x reference)
#include <cuda_runtime.h>

#define D 128
#define TILE_M 64

static constexpr int MAXN = 50000;

// Scratch (allocation-free: __device__ globals)
__device__ float g_Ah[MAXN * D];
__device__ float g_Bh[MAXN * D];
__device__ float g_Dh[MAXN * D];
__device__ float g_Eh[MAXN * D];
__device__ float g_sumMsg[MAXN * D];
__device__ float g_sumSig[MAXN * D];

// smem: Wt (128x128 swizzled transpose) + As (64x128) + src/dst staging
#define SMEM_FLOATS (128 * 128 + TILE_M * 128)
#define SMEM_BYTES  (SMEM_FLOATS * 4 + 2 * TILE_M * 4)

__global__ void zero_kernel(int n4) {
    int i = blockIdx.x * blockDim.x + threadIdx.x;
    if (i < n4) {
        ((float4*)g_sumMsg)[i] = make_float4(0.f, 0.f, 0.f, 0.f);
        ((float4*)g_sumSig)[i] = make_float4(0.f, 0.f, 0.f, 0.f);
    }
}

// ---------------------------------------------------------------------------
// Shared GEMM mainloop: C[64,128] = A[64,128] @ W^T, W row-major [128,128].
// Wt in smem holds W transposed with XOR swizzle: Wt[k*128 + (j ^ (k&31))] = W[j*128+k]
// Thread (tx,ty): rows ty*8+r (r<8), cols tx+32c (c<4). All smem accesses conflict-free.
// ---------------------------------------------------------------------------
__device__ __forceinline__ void gemm_mainloop(const float* __restrict__ Wt,
                                              const float* __restrict__ As,
                                              int tx, int ty, float acc[8][4]) {
#pragma unroll 4
    for (int k = 0; k < 128; ++k) {
        float bv[4];
        int sw = tx ^ (k & 31);
#pragma unroll
        for (int c = 0; c < 4; ++c) bv[c] = Wt[k * 128 + sw + 32 * c];
#pragma unroll
        for (int r = 0; r < 8; ++r) {
            float a = As[(ty * 8 + r) * 128 + k];
#pragma unroll
            for (int c = 0; c < 4; ++c) acc[r][c] += a * bv[c];
        }
    }
}

__device__ __forceinline__ void load_wt(float* Wt, const float* __restrict__ W, int tid) {
    for (int idx = tid; idx < 128 * 128; idx += 256) {
        int j = idx >> 7, k = idx & 127;
        Wt[k * 128 + (j ^ (k & 31))] = W[idx];
    }
}

// ---------------------------------------------------------------------------
// Node GEMMs: Ah/Bh/Dh/Eh = h @ W{A,B,D,E}^T + b  (blockIdx.y selects which)
// ---------------------------------------------------------------------------
__global__ __launch_bounds__(256, 2) void node_gemm_kernel(
    const float* __restrict__ h,
    const float* __restrict__ W0, const float* __restrict__ b0,
    const float* __restrict__ W1, const float* __restrict__ b1,
    const float* __restrict__ W2, const float* __restrict__ b2,
    const float* __restrict__ W3, const float* __restrict__ b3,
    int Nn) {
    extern __shared__ float smem[];
    float* Wt = smem;
    float* As = smem + 128 * 128;

    int which = blockIdx.y;
    const float* W    = (which == 0) ? W0 : (which == 1) ? W1 : (which == 2) ? W2 : W3;
    const float* bias = (which == 0) ? b0 : (which == 1) ? b1 : (which == 2) ? b2 : b3;
    float* out        = (which == 0) ? g_Ah : (which == 1) ? g_Bh : (which == 2) ? g_Dh : g_Eh;

    int row0 = blockIdx.x * TILE_M;
    int tid = threadIdx.x;

    load_wt(Wt, W, tid);
    for (int idx = tid; idx < TILE_M * 128; idx += 256) {
        int r = idx >> 7, c = idx & 127;
        int row = row0 + r;
        As[idx] = (row < Nn) ? h[row * D + c] : 0.f;
    }
    __syncthreads();

    int tx = tid & 31, ty = tid >> 5;
    float acc[8][4] = {};
    gemm_mainloop(Wt, As, tx, ty, acc);

#pragma unroll
    for (int r = 0; r < 8; ++r) {
        int row = row0 + ty * 8 + r;
        if (row < Nn) {
#pragma unroll
            for (int c = 0; c < 4; ++c) {
                int j = tx + 32 * c;
                out[row * D + j] = acc[r][c] + bias[j];
            }
        }
    }
}

// ---------------------------------------------------------------------------
// Fused edge kernel: Ce GEMM + gather(Dh[src],Eh[dst],Bh[src]) + sigmoid +
// e_out + atomic segment sums. e_new never hits HBM.
// ---------------------------------------------------------------------------
__global__ __launch_bounds__(256, 2) void edge_kernel(
    const float* __restrict__ e,
    const int* __restrict__ src, const int* __restrict__ dst,
    const float* __restrict__ WC, const float* __restrict__ bC,
    float* __restrict__ e_out, int Ecnt) {
    extern __shared__ float smem[];
    float* Wt = smem;
    float* As = smem + 128 * 128;
    int* sSrc = (int*)(smem + SMEM_FLOATS);
    int* sDst = sSrc + TILE_M;

    int m0 = blockIdx.x * TILE_M;
    int tid = threadIdx.x;

    load_wt(Wt, WC, tid);
    for (int idx = tid; idx < TILE_M * 128; idx += 256) {
        int r = idx >> 7, c = idx & 127;
        int m = m0 + r;
        As[idx] = (m < Ecnt) ? e[m * D + c] : 0.f;
    }
    if (tid < TILE_M) {
        int m = m0 + tid;
        sSrc[tid] = (m < Ecnt) ? src[m] : 0;
        sDst[tid] = (m < Ecnt) ? dst[m] : 0;
    }
    __syncthreads();

    int tx = tid & 31, ty = tid >> 5;
    float acc[8][4] = {};
    gemm_mainloop(Wt, As, tx, ty, acc);

#pragma unroll
    for (int r = 0; r < 8; ++r) {
        int lr = ty * 8 + r;
        int m = m0 + lr;
        if (m < Ecnt) {
            int s = sSrc[lr], dd = sDst[lr];
            const float* DhS = g_Dh + s * D;
            const float* EhD = g_Eh + dd * D;
            const float* BhS = g_Bh + s * D;
            float* sMsg = g_sumMsg + dd * D;
            float* sSig = g_sumSig + dd * D;
#pragma unroll
            for (int c = 0; c < 4; ++c) {
                int j = tx + 32 * c;
                float x = acc[r][c] + bC[j] + DhS[j] + EhD[j];
                float sg = 1.f / (1.f + __expf(-x));
                e_out[m * D + j] = As[lr * 128 + j] + x * sg;  // e + silu(e_new)
                atomicAdd(&sMsg[j], BhS[j] * sg);
                atomicAdd(&sSig[j], sg);
            }
        }
    }
}

__global__ void node_final_kernel(const float* __restrict__ h,
                                  float* __restrict__ h_out, int nd) {
    int i = blockIdx.x * blockDim.x + threadIdx.x;
    if (i < nd) {
        float x = g_Ah[i] + g_sumMsg[i] / (g_sumSig[i] + 1e-6f);
        float sg = 1.f / (1.f + __expf(-x));
        h_out[i] = h[i] + x * sg;
    }
}

extern "C" void kernel_launch(void* const* d_in, const int* in_sizes, int n_in,
                              void* d_out, int out_size) {
    const float* h   = (const float*)d_in[0];
    const float* e   = (const float*)d_in[1];
    const int*   src = (const int*)d_in[2];
    const int*   dst = (const int*)d_in[3];
    const float* WA = (const float*)d_in[4];  const float* bA = (const float*)d_in[5];
    const float* WB = (const float*)d_in[6];  const float* bB = (const float*)d_in[7];
    const float* WC = (const float*)d_in[8];  const float* bC = (const float*)d_in[9];
    const float* WD = (const float*)d_in[10]; const float* bD = (const float*)d_in[11];
    const float* WE = (const float*)d_in[12]; const float* bE = (const float*)d_in[13];

    int N = in_sizes[0] / D;
    int E = in_sizes[2];

    float* out   = (float*)d_out;
    float* h_out = out;
    float* e_out = out + (size_t)N * D;

    cudaFuncSetAttribute(node_gemm_kernel, cudaFuncAttributeMaxDynamicSharedMemorySize, SMEM_BYTES);
    cudaFuncSetAttribute(edge_kernel,      cudaFuncAttributeMaxDynamicSharedMemorySize, SMEM_BYTES);

    int nd = N * D;
    int n4 = nd / 4;
    zero_kernel<<<(n4 + 255) / 256, 256>>>(n4);

    dim3 ngrid((N + TILE_M - 1) / TILE_M, 4);
    node_gemm_kernel<<<ngrid, 256, SMEM_BYTES>>>(h, WA, bA, WB, bB, WD, bD, WE, bE, N);

    edge_kernel<<<(E + TILE_M - 1) / TILE_M, 256, SMEM_BYTES>>>(e, src, dst, WC, bC, e_out, E);

    node_final_kernel<<<(nd + 255) / 256, 256>>>(h, h_out, nd);
}

// round 2
// speedup vs baseline: 1.1263x; 1.1263x over previous
#include <cuda_runtime.h>

#define D 128
#define TILE_M 64

static constexpr int MAXN = 50000;
static constexpr int MAXE = 600000;

// Scratch (allocation-free: __device__ globals)
__device__ float g_Ah[MAXN * D];
__device__ float g_Bh[MAXN * D];
__device__ float g_Dh[MAXN * D];
__device__ float g_Eh[MAXN * D];
__device__ float g_sig[(size_t)MAXE * D];   // sigma rows, dst-sorted
__device__ int   g_srcs[MAXE];              // src per sorted slot
__device__ int   g_cnt[MAXN];
__device__ int   g_off[MAXN];
__device__ int   g_run[MAXN];
__device__ int   g_chunk[256];

#define SMEM_FLOATS (128 * 128 + TILE_M * 128)
#define SMEM_BYTES  (SMEM_FLOATS * 4 + 2 * TILE_M * 4)

// ---------------------------------------------------------------------------
// Counting sort by dst: zero counts -> histogram -> 2-level exclusive scan
// ---------------------------------------------------------------------------
__global__ void zero_cnt_kernel(int n) {
    int i = blockIdx.x * blockDim.x + threadIdx.x;
    if (i < n) g_cnt[i] = 0;
}

__global__ void hist_kernel(const int* __restrict__ dst, int Ecnt) {
    int i = blockIdx.x * blockDim.x + threadIdx.x;
    if (i < Ecnt) atomicAdd(&g_cnt[dst[i]], 1);
}

__global__ void scan1_kernel(int n) {   // per-512 chunk exclusive scan
    __shared__ int sm[512];
    int tid = threadIdx.x;
    int i = blockIdx.x * 512 + tid;
    int v = (i < n) ? g_cnt[i] : 0;
    sm[tid] = v;
    __syncthreads();
    for (int off = 1; off < 512; off <<= 1) {
        int t = (tid >= off) ? sm[tid - off] : 0;
        __syncthreads();
        sm[tid] += t;
        __syncthreads();
    }
    if (i < n) g_off[i] = sm[tid] - v;
    if (tid == 511) g_chunk[blockIdx.x] = sm[511];
}

__global__ void scan2_kernel(int nchunks) {  // 1 thread: scan chunk totals
    if (threadIdx.x == 0 && blockIdx.x == 0) {
        int acc = 0;
        for (int i = 0; i < nchunks; ++i) {
            int t = g_chunk[i];
            g_chunk[i] = acc;
            acc += t;
        }
    }
}

__global__ void scan3_kernel(int n) {
    int i = blockIdx.x * blockDim.x + threadIdx.x;
    if (i < n) {
        int o = g_off[i] + g_chunk[i >> 9];
        g_off[i] = o;
        g_run[i] = o;
    }
}

// ---------------------------------------------------------------------------
// Shared GEMM mainloop: C[64,128] = A[64,128] @ W^T  (Wt = swizzled transpose)
// ---------------------------------------------------------------------------
__device__ __forceinline__ void gemm_mainloop(const float* __restrict__ Wt,
                                              const float* __restrict__ As,
                                              int tx, int ty, float acc[8][4]) {
#pragma unroll 4
    for (int k = 0; k < 128; ++k) {
        float bv[4];
        int sw = tx ^ (k & 31);
#pragma unroll
        for (int c = 0; c < 4; ++c) bv[c] = Wt[k * 128 + sw + 32 * c];
#pragma unroll
        for (int r = 0; r < 8; ++r) {
            float a = As[(ty * 8 + r) * 128 + k];
#pragma unroll
            for (int c = 0; c < 4; ++c) acc[r][c] += a * bv[c];
        }
    }
}

__device__ __forceinline__ void load_wt(float* Wt, const float* __restrict__ W, int tid) {
    for (int idx = tid; idx < 128 * 128; idx += 256) {
        int j = idx >> 7, k = idx & 127;
        Wt[k * 128 + (j ^ (k & 31))] = W[idx];
    }
}

// ---------------------------------------------------------------------------
// Node GEMMs: Ah/Bh/Dh/Eh = h @ W{A,B,D,E}^T + b
// ---------------------------------------------------------------------------
__global__ __launch_bounds__(256, 2) void node_gemm_kernel(
    const float* __restrict__ h,
    const float* __restrict__ W0, const float* __restrict__ b0,
    const float* __restrict__ W1, const float* __restrict__ b1,
    const float* __restrict__ W2, const float* __restrict__ b2,
    const float* __restrict__ W3, const float* __restrict__ b3,
    int Nn) {
    extern __shared__ float smem[];
    float* Wt = smem;
    float* As = smem + 128 * 128;

    int which = blockIdx.y;
    const float* W    = (which == 0) ? W0 : (which == 1) ? W1 : (which == 2) ? W2 : W3;
    const float* bias = (which == 0) ? b0 : (which == 1) ? b1 : (which == 2) ? b2 : b3;
    float* out        = (which == 0) ? g_Ah : (which == 1) ? g_Bh : (which == 2) ? g_Dh : g_Eh;

    int row0 = blockIdx.x * TILE_M;
    int tid = threadIdx.x;

    load_wt(Wt, W, tid);
    for (int idx = tid; idx < TILE_M * 128; idx += 256) {
        int r = idx >> 7, c = idx & 127;
        int row = row0 + r;
        As[idx] = (row < Nn) ? h[row * D + c] : 0.f;
    }
    __syncthreads();

    int tx = tid & 31, ty = tid >> 5;
    float acc[8][4] = {};
    gemm_mainloop(Wt, As, tx, ty, acc);

#pragma unroll
    for (int r = 0; r < 8; ++r) {
        int row = row0 + ty * 8 + r;
        if (row < Nn) {
#pragma unroll
            for (int c = 0; c < 4; ++c) {
                int j = tx + 32 * c;
                out[row * D + j] = acc[r][c] + bias[j];
            }
        }
    }
}

// ---------------------------------------------------------------------------
// Fused edge kernel: Ce GEMM + gather(Dh[src],Eh[dst]) + sigmoid + e_out +
// scatter sigma into dst-sorted slots (one int atomic per edge).
// ---------------------------------------------------------------------------
__global__ __launch_bounds__(256, 2) void edge_kernel(
    const float* __restrict__ e,
    const int* __restrict__ src, const int* __restrict__ dst,
    const float* __restrict__ WC, const float* __restrict__ bC,
    float* __restrict__ e_out, int Ecnt) {
    extern __shared__ float smem[];
    float* Wt = smem;
    float* As = smem + 128 * 128;
    int* sSrc = (int*)(smem + SMEM_FLOATS);
    int* sDst = sSrc + TILE_M;

    int m0 = blockIdx.x * TILE_M;
    int tid = threadIdx.x;

    load_wt(Wt, WC, tid);
    for (int idx = tid; idx < TILE_M * 128; idx += 256) {
        int r = idx >> 7, c = idx & 127;
        int m = m0 + r;
        As[idx] = (m < Ecnt) ? e[m * D + c] : 0.f;
    }
    if (tid < TILE_M) {
        int m = m0 + tid;
        sSrc[tid] = (m < Ecnt) ? src[m] : 0;
        sDst[tid] = (m < Ecnt) ? dst[m] : 0;
    }
    __syncthreads();

    int tx = tid & 31, ty = tid >> 5;
    float acc[8][4] = {};
    gemm_mainloop(Wt, As, tx, ty, acc);

    float biasv[4];
#pragma unroll
    for (int c = 0; c < 4; ++c) biasv[c] = bC[tx + 32 * c];

#pragma unroll
    for (int r = 0; r < 8; ++r) {
        int lr = ty * 8 + r;
        int m = m0 + lr;
        if (m < Ecnt) {
            int s = sSrc[lr], dd = sDst[lr];
            int pos = 0;
            if (tx == 0) {
                pos = atomicAdd(&g_run[dd], 1);
                g_srcs[pos] = s;
            }
            pos = __shfl_sync(0xffffffff, pos, 0);
            const float* DhS = g_Dh + s * D;
            const float* EhD = g_Eh + dd * D;
            float* sigRow = g_sig + (size_t)pos * D;
#pragma unroll
            for (int c = 0; c < 4; ++c) {
                int j = tx + 32 * c;
                float x = acc[r][c] + biasv[c] + DhS[j] + EhD[j];
                float sg = 1.f / (1.f + __expf(-x));
                e_out[m * D + j] = As[lr * 128 + j] + x * sg;  // e + silu(e_new)
                sigRow[j] = sg;
            }
        }
    }
}

// ---------------------------------------------------------------------------
// Aggregate: per-node segment sums over contiguous sorted sigma rows,
// fused with node_final (h_out = h + silu(Ah + sumMsg/(sumSig+eps)))
// ---------------------------------------------------------------------------
__global__ __launch_bounds__(256) void aggregate_kernel(
    const float* __restrict__ h, float* __restrict__ h_out, int Nn) {
    int node = blockIdx.x * 2 + (threadIdx.x >> 7);
    int j = threadIdx.x & 127;
    if (node >= Nn) return;

    int off = g_off[node];
    int cnt = g_cnt[node];
    float ssig = 0.f, smsg = 0.f;
    for (int i = 0; i < cnt; ++i) {
        float sg = g_sig[(size_t)(off + i) * D + j];
        int s = g_srcs[off + i];
        smsg += g_Bh[s * D + j] * sg;
        ssig += sg;
    }
    float x = g_Ah[node * D + j] + smsg / (ssig + 1e-6f);
    float sgm = 1.f / (1.f + __expf(-x));
    h_out[node * D + j] = h[node * D + j] + x * sgm;
}

extern "C" void kernel_launch(void* const* d_in, const int* in_sizes, int n_in,
                              void* d_out, int out_size) {
    const float* h   = (const float*)d_in[0];
    const float* e   = (const float*)d_in[1];
    const int*   src = (const int*)d_in[2];
    const int*   dst = (const int*)d_in[3];
    const float* WA = (const float*)d_in[4];  const float* bA = (const float*)d_in[5];
    const float* WB = (const float*)d_in[6];  const float* bB = (const float*)d_in[7];
    const float* WC = (const float*)d_in[8];  const float* bC = (const float*)d_in[9];
    const float* WD = (const float*)d_in[10]; const float* bD = (const float*)d_in[11];
    const float* WE = (const float*)d_in[12]; const float* bE = (const float*)d_in[13];

    int N = in_sizes[0] / D;
    int E = in_sizes[2];

    float* out   = (float*)d_out;
    float* h_out = out;
    float* e_out = out + (size_t)N * D;

    cudaFuncSetAttribute(node_gemm_kernel, cudaFuncAttributeMaxDynamicSharedMemorySize, SMEM_BYTES);
    cudaFuncSetAttribute(edge_kernel,      cudaFuncAttributeMaxDynamicSharedMemorySize, SMEM_BYTES);

    // counting sort by dst
    zero_cnt_kernel<<<(N + 255) / 256, 256>>>(N);
    hist_kernel<<<(E + 255) / 256, 256>>>(dst, E);
    int nchunks = (N + 511) / 512;
    scan1_kernel<<<nchunks, 512>>>(N);
    scan2_kernel<<<1, 32>>>(nchunks);
    scan3_kernel<<<(N + 255) / 256, 256>>>(N);

    // node GEMMs
    dim3 ngrid((N + TILE_M - 1) / TILE_M, 4);
    node_gemm_kernel<<<ngrid, 256, SMEM_BYTES>>>(h, WA, bA, WB, bB, WD, bD, WE, bE, N);

    // fused edge GEMM + epilogue + sigma scatter
    edge_kernel<<<(E + TILE_M - 1) / TILE_M, 256, SMEM_BYTES>>>(e, src, dst, WC, bC, e_out, E);

    // segment sums + node update
    aggregate_kernel<<<(N + 1) / 2, 256>>>(h, h_out, N);
}

// round 4
// speedup vs baseline: 1.5427x; 1.3697x over previous
#include <cuda_runtime.h>
#include <cuda_bf16.h>
#include <cstdint>

#define D 128
#define TILE_M 128

static constexpr int MAXN = 50000;
static constexpr int MAXE = 600000;

// Scratch (allocation-free: __device__ globals)
__device__ float g_Ah[MAXN * D];
__device__ float g_Bh[MAXN * D];
__device__ float g_Dh[MAXN * D];
__device__ float g_Eh[MAXN * D];
__device__ float g_sig[(size_t)MAXE * D];   // sigma rows, dst-sorted
__device__ int   g_srcs[MAXE];              // src per sorted slot
__device__ int   g_cnt[MAXN];
__device__ int   g_off[MAXN];
__device__ int   g_run[MAXN];
__device__ int   g_chunk[256];

// ---------------------------------------------------------------------------
// SMEM layout (dynamic): [align 1024] a_hi(32K) a_lo(32K) b_hi(32K) b_lo(32K) ctrl(2K)
// After the MMA mainloop, the b_hi/b_lo region (64K) is reused as the fp32 C tile.
// ---------------------------------------------------------------------------
#define T_BYTES 32768
#define SMEM_DYN (1024 + 4 * T_BYTES + 2048)
#define OFF_AHI 0
#define OFF_ALO (T_BYTES)
#define OFF_BHI (2 * T_BYTES)
#define OFF_CSM (2 * T_BYTES)
#define OFF_BLO (3 * T_BYTES)
#define OFF_CTRL (4 * T_BYTES)

__device__ __forceinline__ uint32_t smem_u32(const void* p) {
    uint32_t a;
    asm("{ .reg .u64 t; cvta.to.shared.u64 t, %1; cvt.u32.u64 %0, t; }" : "=r"(a) : "l"(p));
    return a;
}

// bf16 tile swizzle: row-major [128][128] bf16, 256B rows, 16B-atom XOR swizzle
__device__ __forceinline__ uint32_t sw256(int r, int cbyte) {
    uint32_t o = (uint32_t)r * 256u + (uint32_t)cbyte;
    return o ^ (((uint32_t)r & 7u) << 4);
}
// fp32 C tile swizzle: 512B rows
__device__ __forceinline__ uint32_t sw512(int r, int cbyte) {
    uint32_t o = (uint32_t)r * 512u + (uint32_t)cbyte;
    return o ^ (((uint32_t)r & 7u) << 4);
}

__device__ __forceinline__ void ldm4(uint32_t addr, uint32_t r[4]) {
    asm volatile("ldmatrix.sync.aligned.m8n8.x4.shared.b16 {%0,%1,%2,%3}, [%4];"
                 : "=r"(r[0]), "=r"(r[1]), "=r"(r[2]), "=r"(r[3]) : "r"(addr));
}

__device__ __forceinline__ void mma16816(float c[4], const uint32_t a[4],
                                         uint32_t b0, uint32_t b1) {
    asm volatile("mma.sync.aligned.m16n8k16.row.col.f32.bf16.bf16.f32 "
                 "{%0,%1,%2,%3}, {%4,%5,%6,%7}, {%8,%9}, {%0,%1,%2,%3};"
                 : "+f"(c[0]), "+f"(c[1]), "+f"(c[2]), "+f"(c[3])
                 : "r"(a[0]), "r"(a[1]), "r"(a[2]), "r"(a[3]), "r"(b0), "r"(b1));
}

// Load a [cnt x 128] fp32 tile -> hi/lo bf16 swizzled tiles. thread t: row t>>1, 64 cols.
__device__ __forceinline__ void load_tile_hilo(char* hi_base, char* lo_base,
                                               const float* __restrict__ srcp,
                                               int row0, int cnt, int tid) {
    int r = tid >> 1;
    int c0 = (tid & 1) * 64;
    int grow = row0 + r;
    const float4* rowp = (const float4*)(srcp + (size_t)grow * D);
#pragma unroll
    for (int i = 0; i < 16; ++i) {
        int k = c0 + i * 4;
        float4 v = (grow < cnt) ? rowp[k >> 2] : make_float4(0.f, 0.f, 0.f, 0.f);
        __nv_bfloat16 h0 = __float2bfloat16(v.x);
        __nv_bfloat16 h1 = __float2bfloat16(v.y);
        __nv_bfloat16 h2 = __float2bfloat16(v.z);
        __nv_bfloat16 h3 = __float2bfloat16(v.w);
        __nv_bfloat16 l0 = __float2bfloat16(v.x - __bfloat162float(h0));
        __nv_bfloat16 l1 = __float2bfloat16(v.y - __bfloat162float(h1));
        __nv_bfloat16 l2 = __float2bfloat16(v.z - __bfloat162float(h2));
        __nv_bfloat16 l3 = __float2bfloat16(v.w - __bfloat162float(h3));
        uint32_t o0 = sw256(r, k * 2);
        uint32_t o1 = sw256(r, k * 2 + 4);
        *(__nv_bfloat162*)(hi_base + o0) = __nv_bfloat162(h0, h1);
        *(__nv_bfloat162*)(hi_base + o1) = __nv_bfloat162(h2, h3);
        *(__nv_bfloat162*)(lo_base + o0) = __nv_bfloat162(l0, l1);
        *(__nv_bfloat162*)(lo_base + o1) = __nv_bfloat162(l2, l3);
    }
}

// ---------------------------------------------------------------------------
// MMA mainloop: C[128,128] = A @ W^T using 3-term bf16 split.
// Warp w: rows (w&3)*32..+31 (2 m-tiles), cols (w>>2)*64..+63 (8 n-tiles).
// ---------------------------------------------------------------------------
__device__ __forceinline__ void gemm_mma(uint32_t AL, int tid, float acc[2][8][4]) {
    int lane = tid & 31, wid = tid >> 5;
    int mtb = (wid & 3) * 32;
    int ntb = (wid >> 2) * 64;
    int lrow = lane & 15;
    int lkoff = (lane >> 4) * 16;   // byte offset for k-half

#pragma unroll
    for (int kc = 0; kc < 8; ++kc) {
        int kb = kc * 32;   // byte offset of this 16-wide k chunk
        uint32_t ah[2][4], al[2][4];
#pragma unroll
        for (int mt = 0; mt < 2; ++mt) {
            uint32_t so = sw256(mtb + mt * 16 + lrow, kb + lkoff);
            ldm4(AL + OFF_AHI + so, ah[mt]);
            ldm4(AL + OFF_ALO + so, al[mt]);
        }
#pragma unroll
        for (int ntp = 0; ntp < 4; ++ntp) {
            uint32_t so = sw256(ntb + ntp * 16 + lrow, kb + lkoff);
            uint32_t bh[4], bl[4];
            ldm4(AL + OFF_BHI + so, bh);
            ldm4(AL + OFF_BLO + so, bl);
#pragma unroll
            for (int mt = 0; mt < 2; ++mt) {
#pragma unroll
                for (int q = 0; q < 2; ++q) {
                    float* c = acc[mt][ntp * 2 + q];
                    mma16816(c, ah[mt], bh[q], bh[q + 2]);
                    mma16816(c, ah[mt], bl[q], bl[q + 2]);
                    mma16816(c, al[mt], bh[q], bh[q + 2]);
                }
            }
        }
    }
}

// Write accumulators into the fp32 C smem tile (reuses W region; caller syncs first).
__device__ __forceinline__ void store_c(char* lbase, int tid, float acc[2][8][4]) {
    int lane = tid & 31, wid = tid >> 5;
    int mtb = (wid & 3) * 32;
    int ntb = (wid >> 2) * 64;
#pragma unroll
    for (int mt = 0; mt < 2; ++mt) {
#pragma unroll
        for (int nt = 0; nt < 8; ++nt) {
            int r0 = mtb + mt * 16 + (lane >> 2);
            int cb = (ntb + nt * 8 + (lane & 3) * 2) * 4;
            float* c = acc[mt][nt];
            *(float2*)(lbase + OFF_CSM + sw512(r0, cb))     = make_float2(c[0], c[1]);
            *(float2*)(lbase + OFF_CSM + sw512(r0 + 8, cb)) = make_float2(c[2], c[3]);
        }
    }
}

// ---------------------------------------------------------------------------
// Counting sort by dst
// ---------------------------------------------------------------------------
__global__ void zero_cnt_kernel(int n) {
    int i = blockIdx.x * blockDim.x + threadIdx.x;
    if (i < n) g_cnt[i] = 0;
}
__global__ void hist_kernel(const int* __restrict__ dst, int Ecnt) {
    int i = blockIdx.x * blockDim.x + threadIdx.x;
    if (i < Ecnt) atomicAdd(&g_cnt[dst[i]], 1);
}
__global__ void scan1_kernel(int n) {
    __shared__ int sm[512];
    int tid = threadIdx.x;
    int i = blockIdx.x * 512 + tid;
    int v = (i < n) ? g_cnt[i] : 0;
    sm[tid] = v;
    __syncthreads();
    for (int off = 1; off < 512; off <<= 1) {
        int t = (tid >= off) ? sm[tid - off] : 0;
        __syncthreads();
        sm[tid] += t;
        __syncthreads();
    }
    if (i < n) g_off[i] = sm[tid] - v;
    if (tid == 511) g_chunk[blockIdx.x] = sm[511];
}
__global__ void scan2_kernel(int nchunks) {
    if (threadIdx.x == 0 && blockIdx.x == 0) {
        int acc = 0;
        for (int i = 0; i < nchunks; ++i) { int t = g_chunk[i]; g_chunk[i] = acc; acc += t; }
    }
}
__global__ void scan3_kernel(int n) {
    int i = blockIdx.x * blockDim.x + threadIdx.x;
    if (i < n) { int o = g_off[i] + g_chunk[i >> 9]; g_off[i] = o; g_run[i] = o; }
}

// ---------------------------------------------------------------------------
// Node GEMMs (mma.sync): out = h @ W^T + b for W in {WA, WB, WD, WE}
// ---------------------------------------------------------------------------
__global__ __launch_bounds__(256, 1) void node_gemm_kernel(
    const float* __restrict__ h,
    const float* __restrict__ W0, const float* __restrict__ b0,
    const float* __restrict__ W1, const float* __restrict__ b1,
    const float* __restrict__ W2, const float* __restrict__ b2,
    const float* __restrict__ W3, const float* __restrict__ b3,
    int Nn) {
    extern __shared__ char smem[];
    uint32_t sbase = smem_u32(smem);
    uint32_t AL = (sbase + 1023) & ~1023u;
    char* lbase = smem + (AL - sbase);

    int which = blockIdx.y;
    const float* W    = (which == 0) ? W0 : (which == 1) ? W1 : (which == 2) ? W2 : W3;
    const float* bias = (which == 0) ? b0 : (which == 1) ? b1 : (which == 2) ? b2 : b3;
    float* out        = (which == 0) ? g_Ah : (which == 1) ? g_Bh : (which == 2) ? g_Dh : g_Eh;

    int tid = threadIdx.x;
    int row0 = blockIdx.x * TILE_M;

    load_tile_hilo(lbase + OFF_AHI, lbase + OFF_ALO, h, row0, Nn, tid);
    load_tile_hilo(lbase + OFF_BHI, lbase + OFF_BLO, W, 0, 128, tid);
    __syncthreads();

    float acc[2][8][4] = {};
    gemm_mma(AL, tid, acc);
    __syncthreads();           // all B-fragment reads done before overwriting with C
    store_c(lbase, tid, acc);
    __syncthreads();

    int r = tid >> 1;
    int ch = tid & 1;
    int row = row0 + r;
    if (row < Nn) {
        float* orow = out + (size_t)row * D;
#pragma unroll
        for (int i = 0; i < 16; ++i) {
            int col = ch * 64 + i * 4;
            float4 c4 = *(const float4*)(lbase + OFF_CSM + sw512(r, col * 4));
            float4 b4 = *(const float4*)(bias + col);
            *(float4*)(orow + col) = make_float4(c4.x + b4.x, c4.y + b4.y,
                                                 c4.z + b4.z, c4.w + b4.w);
        }
    }
}

// ---------------------------------------------------------------------------
// Fused edge kernel: Ce GEMM + gather(Dh[src],Eh[dst]) + sigmoid + e_out + sigma scatter
// ---------------------------------------------------------------------------
__global__ __launch_bounds__(256, 1) void edge_kernel(
    const float* __restrict__ e,
    const int* __restrict__ src, const int* __restrict__ dst,
    const float* __restrict__ WC, const float* __restrict__ bC,
    float* __restrict__ e_out, int Ecnt) {
    extern __shared__ char smem[];
    uint32_t sbase = smem_u32(smem);
    uint32_t AL = (sbase + 1023) & ~1023u;
    char* lbase = smem + (AL - sbase);

    int tid = threadIdx.x;
    int m0 = blockIdx.x * TILE_M;

    int* sSrc = (int*)(lbase + OFF_CTRL);
    int* sDst = (int*)(lbase + OFF_CTRL + 512);
    int* sPos = (int*)(lbase + OFF_CTRL + 1024);

    load_tile_hilo(lbase + OFF_AHI, lbase + OFF_ALO, e, m0, Ecnt, tid);
    load_tile_hilo(lbase + OFF_BHI, lbase + OFF_BLO, WC, 0, 128, tid);
    if (tid < TILE_M) {
        int m = m0 + tid;
        sSrc[tid] = (m < Ecnt) ? src[m] : 0;
        sDst[tid] = (m < Ecnt) ? dst[m] : 0;
    }
    __syncthreads();

    float acc[2][8][4] = {};
    gemm_mma(AL, tid, acc);
    __syncthreads();
    store_c(lbase, tid, acc);

    // claim dst-sorted slots (one int atomic per edge, from the even thread of each row)
    int r = tid >> 1;
    int ch = tid & 1;
    int m = m0 + r;
    if (ch == 0 && m < Ecnt) {
        int dd = sDst[r];
        int p = atomicAdd(&g_run[dd], 1);
        g_srcs[p] = sSrc[r];
        sPos[r] = p;
    }
    __syncthreads();

    if (m < Ecnt) {
        int s = sSrc[r], dd = sDst[r];
        int pos = sPos[r];
        const float* DhS = g_Dh + (size_t)s * D;
        const float* EhD = g_Eh + (size_t)dd * D;
        float* eo = e_out + (size_t)m * D;
        float* sigRow = g_sig + (size_t)pos * D;
        char* ahb = lbase + OFF_AHI;
        char* alb = lbase + OFF_ALO;
#pragma unroll
        for (int i = 0; i < 16; ++i) {
            int col = ch * 64 + i * 4;
            float4 c4 = *(const float4*)(lbase + OFF_CSM + sw512(r, col * 4));
            float4 b4 = *(const float4*)(bC + col);
            float4 dh = *(const float4*)(DhS + col);
            float4 eh = *(const float4*)(EhD + col);
            // reconstruct e = hi + lo from smem tiles
            uint32_t o0 = sw256(r, col * 2);
            uint32_t o1 = sw256(r, col * 2 + 4);
            __nv_bfloat162 h01 = *(__nv_bfloat162*)(ahb + o0);
            __nv_bfloat162 h23 = *(__nv_bfloat162*)(ahb + o1);
            __nv_bfloat162 l01 = *(__nv_bfloat162*)(alb + o0);
            __nv_bfloat162 l23 = *(__nv_bfloat162*)(alb + o1);
            float e0 = __bfloat162float(h01.x) + __bfloat162float(l01.x);
            float e1 = __bfloat162float(h01.y) + __bfloat162float(l01.y);
            float e2 = __bfloat162float(h23.x) + __bfloat162float(l23.x);
            float e3 = __bfloat162float(h23.y) + __bfloat162float(l23.y);

            float x0 = c4.x + b4.x + dh.x + eh.x;
            float x1 = c4.y + b4.y + dh.y + eh.y;
            float x2 = c4.z + b4.z + dh.z + eh.z;
            float x3 = c4.w + b4.w + dh.w + eh.w;
            float s0 = 1.f / (1.f + __expf(-x0));
            float s1 = 1.f / (1.f + __expf(-x1));
            float s2 = 1.f / (1.f + __expf(-x2));
            float s3 = 1.f / (1.f + __expf(-x3));
            *(float4*)(eo + col)     = make_float4(e0 + x0 * s0, e1 + x1 * s1,
                                                   e2 + x2 * s2, e3 + x3 * s3);
            *(float4*)(sigRow + col) = make_float4(s0, s1, s2, s3);
        }
    }
}

// ---------------------------------------------------------------------------
// Aggregate: per-node segment sums over contiguous sorted sigma rows,
// fused with node_final (h_out = h + silu(Ah + sumMsg/(sumSig+eps)))
// ---------------------------------------------------------------------------
__global__ __launch_bounds__(256) void aggregate_kernel(
    const float* __restrict__ h, float* __restrict__ h_out, int Nn) {
    int node = blockIdx.x * 2 + (threadIdx.x >> 7);
    int j = threadIdx.x & 127;
    if (node >= Nn) return;

    int off = g_off[node];
    int cnt = g_cnt[node];
    float ssig = 0.f, smsg = 0.f;
    for (int i = 0; i < cnt; ++i) {
        float sg = g_sig[(size_t)(off + i) * D + j];
        int s = g_srcs[off + i];
        smsg += g_Bh[(size_t)s * D + j] * sg;
        ssig += sg;
    }
    float x = g_Ah[(size_t)node * D + j] + smsg / (ssig + 1e-6f);
    float sgm = 1.f / (1.f + __expf(-x));
    h_out[(size_t)node * D + j] = h[(size_t)node * D + j] + x * sgm;
}

extern "C" void kernel_launch(void* const* d_in, const int* in_sizes, int n_in,
                              void* d_out, int out_size) {
    const float* h   = (const float*)d_in[0];
    const float* e   = (const float*)d_in[1];
    const int*   src = (const int*)d_in[2];
    const int*   dst = (const int*)d_in[3];
    const float* WA = (const float*)d_in[4];  const float* bA = (const float*)d_in[5];
    const float* WB = (const float*)d_in[6];  const float* bB = (const float*)d_in[7];
    const float* WC = (const float*)d_in[8];  const float* bC = (const float*)d_in[9];
    const float* WD = (const float*)d_in[10]; const float* bD = (const float*)d_in[11];
    const float* WE = (const float*)d_in[12]; const float* bE = (const float*)d_in[13];

    int N = in_sizes[0] / D;
    int E = in_sizes[2];

    float* out   = (float*)d_out;
    float* h_out = out;
    float* e_out = out + (size_t)N * D;

    cudaFuncSetAttribute(node_gemm_kernel, cudaFuncAttributeMaxDynamicSharedMemorySize, SMEM_DYN);
    cudaFuncSetAttribute(edge_kernel,      cudaFuncAttributeMaxDynamicSharedMemorySize, SMEM_DYN);

    // counting sort by dst
    zero_cnt_kernel<<<(N + 255) / 256, 256>>>(N);
    hist_kernel<<<(E + 255) / 256, 256>>>(dst, E);
    int nchunks = (N + 511) / 512;
    scan1_kernel<<<nchunks, 512>>>(N);
    scan2_kernel<<<1, 32>>>(nchunks);
    scan3_kernel<<<(N + 255) / 256, 256>>>(N);

    // node GEMMs (tensor cores via mma.sync)
    dim3 ngrid((N + TILE_M - 1) / TILE_M, 4);
    node_gemm_kernel<<<ngrid, 256, SMEM_DYN>>>(h, WA, bA, WB, bB, WD, bD, WE, bE, N);

    // fused edge GEMM + epilogue + sigma scatter
    edge_kernel<<<(E + TILE_M - 1) / TILE_M, 256, SMEM_DYN>>>(e, src, dst, WC, bC, e_out, E);

    // segment sums + node update
    aggregate_kernel<<<(N + 1) / 2, 256>>>(h, h_out, N);
}